// round 15
// baseline (speedup 1.0000x reference)
#include <cuda_runtime.h>
#include <cuda_bf16.h>
#include <math.h>
#include <stdint.h>

// ---------------- problem constants ----------------
#define BB 32
#define CC 2048
#define CCW 1024    // CC/2 packed words
#define HH 48
#define WW 24
#define PP 3
#define ICC 128     // IC
#define C4 512
#define PHH 16
#define HD 8
#define WD 12
#define NN 96       // HD*WD
#define BN3 3072    // BB*NN
#define BN3W 1536   // BN3/2 packed words

// ---------------- scratch (device globals; no allocs allowed) ----------------
__device__ uint32_t d_xdT2 [(size_t)PP*BN3*CCW];  // (P,B*N,C/2) bf16x2
__device__ int8_t   d_xq8  [(size_t)PP*BN3*CC];   // (P,B*N,C) int8
__device__ int8_t   d_wq8  [(size_t)PP*CC*CC];    // Wv int8
__device__ float    d_sXd  [(size_t)PP*BN3];      // per-token scale
__device__ float    d_sWv  [(size_t)PP*CC];       // per-Wv-row scale
__device__ uint32_t d_u2   [(size_t)PP*CC*BN3W];  // (P,C,B*N/2) bf16x2 : u = Wv@xd
__device__ float    d_ao   [(size_t)PP*CC*BN3];   // (P,C,B*N)
__device__ float    d_qk   [(size_t)PP*256*BN3];  // (P,256,B*N)
__device__ uint32_t d_wqk2 [(size_t)PP*256*CCW];  // fused q/k weights bf16x2
__device__ float    d_qkb  [(size_t)PP*256];
__device__ uint32_t d_attn2[(size_t)BB*PP*NN*48]; // attn[i][j] bf16x2
__device__ float    d_xsum [(size_t)PP*CC*BB];
__device__ float    d_gap  [(size_t)PP*CC*BB];
__device__ float    d_h1   [(size_t)PP*C4*BB];
__device__ float    d_cw   [(size_t)PP*CC*BB];
__device__ float    d_mw   [BB*PP];

// ---------------- packed fp32x2 helpers ----------------
__device__ __forceinline__ unsigned long long pk2(float lo, float hi){
    unsigned long long r;
    asm("mov.b64 %0, {%1, %2};" : "=l"(r) : "f"(lo), "f"(hi));
    return r;
}
__device__ __forceinline__ unsigned long long ffma2(unsigned long long a, unsigned long long b, unsigned long long c){
    unsigned long long d;
    asm("fma.rn.f32x2 %0, %1, %2, %3;" : "=l"(d) : "l"(a), "l"(b), "l"(c));
    return d;
}
__device__ __forceinline__ float2 upk2(unsigned long long v){
    float2 f;
    asm("mov.b64 {%0, %1}, %2;" : "=f"(f.x), "=f"(f.y) : "l"(v));
    return f;
}

// ---------------- bf16 / mma helpers ----------------
__device__ __forceinline__ uint32_t pack_bf2(float lo, float hi){
    __nv_bfloat162 v = __float22bfloat162_rn(make_float2(lo, hi));
    return *reinterpret_cast<uint32_t*>(&v);
}
__device__ __forceinline__ void mma_bf16(float* c, const uint32_t* a, uint32_t b0, uint32_t b1){
    asm volatile("mma.sync.aligned.m16n8k16.row.col.f32.bf16.bf16.f32 "
        "{%0,%1,%2,%3}, {%4,%5,%6,%7}, {%8,%9}, {%0,%1,%2,%3};"
        : "+f"(c[0]), "+f"(c[1]), "+f"(c[2]), "+f"(c[3])
        : "r"(a[0]), "r"(a[1]), "r"(a[2]), "r"(a[3]), "r"(b0), "r"(b1));
}
__device__ __forceinline__ void mma_s8(int* c, const uint32_t* a, uint32_t b0, uint32_t b1){
    asm volatile("mma.sync.aligned.m16n8k32.row.col.s32.s8.s8.s32 "
        "{%0,%1,%2,%3}, {%4,%5,%6,%7}, {%8,%9}, {%0,%1,%2,%3};"
        : "+r"(c[0]), "+r"(c[1]), "+r"(c[2]), "+r"(c[3])
        : "r"(a[0]), "r"(a[1]), "r"(a[2]), "r"(a[3]), "r"(b0), "r"(b1));
}
__device__ __forceinline__ void ldsm4(uint32_t* r, uint32_t addr){
    asm volatile("ldmatrix.sync.aligned.m8n8.x4.shared.b16 {%0,%1,%2,%3}, [%4];"
        : "=r"(r[0]), "=r"(r[1]), "=r"(r[2]), "=r"(r[3]) : "r"(addr));
}
__device__ __forceinline__ uint32_t smem_u32(const void* p){
    uint32_t a;
    asm("{ .reg .u64 t; cvta.to.shared.u64 t, %1; cvt.u32.u64 %0, t; }" : "=r"(a) : "l"(p));
    return a;
}
__device__ __forceinline__ void cp16(uint32_t dst, const void* src){
    asm volatile("cp.async.cg.shared.global [%0], [%1], 16;" :: "r"(dst), "l"(src));
}
#define CP_COMMIT() asm volatile("cp.async.commit_group;" ::: "memory")
#define CP_WAIT(n)  asm volatile("cp.async.wait_group %0;" :: "n"(n) : "memory")

__device__ __forceinline__ int q8(float v, float inv){
    int q = __float2int_rn(v * inv);
    return q > 127 ? 127 : (q < -127 ? -127 : q);
}
__device__ __forceinline__ uint32_t packs8(int a, int b, int c, int d){
    return (uint32_t)(a & 255) | ((uint32_t)(b & 255) << 8) |
           ((uint32_t)(c & 255) << 16) | ((uint32_t)d << 24);
}

// ============================================================================
// bf16 mma.sync GEMM (qk path): C[M,N] = sum_k A[m,k]*B[n,k] + bias[m]
// ============================================================================
#define BG_ROWB 144
#define BG_BOFF (128*BG_ROWB)
#define BG_STAGE (256*BG_ROWB)
#define BG_SMEM (3*BG_STAGE)

__global__ void __launch_bounds__(128, 2)
bmma_gemm(const uint32_t* __restrict__ A2, const uint32_t* __restrict__ B2,
          float* __restrict__ Cout, const float* __restrict__ bias,
          int N, int Kw, long long sA, long long sB, long long sC, int sBias)
{
    extern __shared__ float smf[];
    const uint32_t su = smem_u32(smf);
    const int tid = threadIdx.x;
    const int p = blockIdx.z;
    const int bm = blockIdx.y * 128, bn = blockIdx.x * 128;
    const uint32_t* Ap = A2 + (size_t)p * sA + (size_t)bm * Kw;
    const uint32_t* Bp = B2 + (size_t)p * sB + (size_t)bn * Kw;

    const int lane = tid & 31, warp = tid >> 5;
    const int wm = (warp & 1) * 64, wn = (warp >> 1) * 64;

    float acc[4][8][4];
    #pragma unroll
    for (int mt=0; mt<4; mt++)
        #pragma unroll
        for (int nt=0; nt<8; nt++)
            #pragma unroll
            for (int r=0; r<4; r++) acc[mt][nt][r] = 0.f;

    const int row0 = tid >> 3, seg = tid & 7;

    auto load = [&](int kw0, int s){
        const uint32_t base = su + s * BG_STAGE;
        #pragma unroll
        for (int i = 0; i < 8; i++)
            cp16(base + (row0 + i*16)*BG_ROWB + seg*16,
                 Ap + (size_t)(row0 + i*16)*Kw + kw0 + seg*4);
        #pragma unroll
        for (int i = 0; i < 8; i++)
            cp16(base + BG_BOFF + (row0 + i*16)*BG_ROWB + seg*16,
                 Bp + (size_t)(row0 + i*16)*Kw + kw0 + seg*4);
        CP_COMMIT();
    };

    const uint32_t aLane = su + (wm + (lane & 15))*BG_ROWB + (lane >> 4)*16;
    const uint32_t bLane = su + BG_BOFF + (wn + ((lane >> 4) << 3) + (lane & 7))*BG_ROWB
                              + ((lane >> 3) & 1)*16;

    const int nC = Kw / 32;
    load(0, 0);
    load(32, 1);
    for (int i = 0; i < nC; i++) {
        const int s = i % 3;
        if (i + 1 < nC) { CP_WAIT(1); } else { CP_WAIT(0); }
        __syncthreads();
        if (i + 2 < nC) load((i+2)*32, (i+2)%3);
        const uint32_t aS = aLane + s*BG_STAGE;
        const uint32_t bS = bLane + s*BG_STAGE;
        #pragma unroll
        for (int k = 0; k < 4; k++) {
            uint32_t a[4][4], bq[4][4];
            #pragma unroll
            for (int mt = 0; mt < 4; mt++)
                ldsm4(a[mt], aS + mt*16*BG_ROWB + k*32);
            #pragma unroll
            for (int ntp = 0; ntp < 4; ntp++)
                ldsm4(bq[ntp], bS + ntp*16*BG_ROWB + k*32);
            #pragma unroll
            for (int mt = 0; mt < 4; mt++)
                #pragma unroll
                for (int ntp = 0; ntp < 4; ntp++) {
                    mma_bf16(acc[mt][2*ntp],   a[mt], bq[ntp][0], bq[ntp][1]);
                    mma_bf16(acc[mt][2*ntp+1], a[mt], bq[ntp][2], bq[ntp][3]);
                }
        }
    }

    const int g = lane >> 2, t = lane & 3;
    const float* bp = bias + (size_t)p * sBias + bm;
    float* Cp = Cout + (size_t)p * sC + (size_t)bm * N + bn;
    #pragma unroll
    for (int mt = 0; mt < 4; mt++) {
        const int r0 = wm + mt*16 + g;
        const float bv0 = bp[r0], bv1 = bp[r0 + 8];
        #pragma unroll
        for (int nt = 0; nt < 8; nt++) {
            const int col = wn + nt*8 + 2*t;
            float2 v0 = make_float2(acc[mt][nt][0] + bv0, acc[mt][nt][1] + bv0);
            float2 v1 = make_float2(acc[mt][nt][2] + bv1, acc[mt][nt][3] + bv1);
            *reinterpret_cast<float2*>(Cp + (size_t)r0*N + col)     = v0;
            *reinterpret_cast<float2*>(Cp + (size_t)(r0+8)*N + col) = v1;
        }
    }
}

// ============================================================================
// int8 mma.sync GEMM (u path): u[m,n] = (sum_k qA[m,k]*qB[n,k]) * sA[m]*sB[n]
// Same geometry as bf16 kernel; K in bytes (2048), chunk = 128B, nC = 16.
// Output packed bf16x2.
// ============================================================================
__global__ void __launch_bounds__(128, 2)
imma_gemm(const int8_t* __restrict__ A8, const int8_t* __restrict__ B8,
          const float* __restrict__ sWv, const float* __restrict__ sXd,
          uint32_t* __restrict__ Uout)
{
    extern __shared__ float smf[];
    const uint32_t su = smem_u32(smf);
    const int tid = threadIdx.x;
    const int p = blockIdx.z;
    const int bm = blockIdx.y * 128, bn = blockIdx.x * 128;
    const int8_t* Ap = A8 + (size_t)p * CC * CC + (size_t)bm * CC;
    const int8_t* Bp = B8 + (size_t)p * BN3 * CC + (size_t)bn * CC;

    const int lane = tid & 31, warp = tid >> 5;
    const int wm = (warp & 1) * 64, wn = (warp >> 1) * 64;

    int acc[4][8][4];
    #pragma unroll
    for (int mt=0; mt<4; mt++)
        #pragma unroll
        for (int nt=0; nt<8; nt++)
            #pragma unroll
            for (int r=0; r<4; r++) acc[mt][nt][r] = 0;

    const int row0 = tid >> 3, seg = tid & 7;

    auto load = [&](int kb0, int s){
        const uint32_t base = su + s * BG_STAGE;
        #pragma unroll
        for (int i = 0; i < 8; i++)
            cp16(base + (row0 + i*16)*BG_ROWB + seg*16,
                 Ap + (size_t)(row0 + i*16)*CC + kb0 + seg*16);
        #pragma unroll
        for (int i = 0; i < 8; i++)
            cp16(base + BG_BOFF + (row0 + i*16)*BG_ROWB + seg*16,
                 Bp + (size_t)(row0 + i*16)*CC + kb0 + seg*16);
        CP_COMMIT();
    };

    const uint32_t aLane = su + (wm + (lane & 15))*BG_ROWB + (lane >> 4)*16;
    const uint32_t bLane = su + BG_BOFF + (wn + ((lane >> 4) << 3) + (lane & 7))*BG_ROWB
                              + ((lane >> 3) & 1)*16;

    const int nC = CC / 128;   // 16 chunks of 128 bytes
    load(0, 0);
    load(128, 1);
    for (int i = 0; i < nC; i++) {
        const int s = i % 3;
        if (i + 1 < nC) { CP_WAIT(1); } else { CP_WAIT(0); }
        __syncthreads();
        if (i + 2 < nC) load((i+2)*128, (i+2)%3);
        const uint32_t aS = aLane + s*BG_STAGE;
        const uint32_t bS = bLane + s*BG_STAGE;
        #pragma unroll
        for (int k = 0; k < 4; k++) {          // 4 k32-steps (32B each)
            uint32_t a[4][4], bq[4][4];
            #pragma unroll
            for (int mt = 0; mt < 4; mt++)
                ldsm4(a[mt], aS + mt*16*BG_ROWB + k*32);
            #pragma unroll
            for (int ntp = 0; ntp < 4; ntp++)
                ldsm4(bq[ntp], bS + ntp*16*BG_ROWB + k*32);
            #pragma unroll
            for (int mt = 0; mt < 4; mt++)
                #pragma unroll
                for (int ntp = 0; ntp < 4; ntp++) {
                    mma_s8(acc[mt][2*ntp],   a[mt], bq[ntp][0], bq[ntp][1]);
                    mma_s8(acc[mt][2*ntp+1], a[mt], bq[ntp][2], bq[ntp][3]);
                }
        }
    }

    const int g = lane >> 2, t = lane & 3;
    const float* sAp = sWv + (size_t)p * CC + bm;
    const float* sBp = sXd + (size_t)p * BN3 + bn;
    uint32_t* Cp = Uout + (size_t)p * CC * BN3W + (size_t)bm * BN3W + (bn >> 1);
    #pragma unroll
    for (int mt = 0; mt < 4; mt++) {
        const int r0 = wm + mt*16 + g;
        const float sa0 = sAp[r0], sa1 = sAp[r0 + 8];
        #pragma unroll
        for (int nt = 0; nt < 8; nt++) {
            const int col = wn + nt*8 + 2*t;
            const float sb0 = sBp[col], sb1 = sBp[col + 1];
            const int colw = col >> 1;
            Cp[(size_t)r0*BN3W + colw] =
                pack_bf2((float)acc[mt][nt][0]*sa0*sb0, (float)acc[mt][nt][1]*sa0*sb1);
            Cp[(size_t)(r0+8)*BN3W + colw] =
                pack_bf2((float)acc[mt][nt][2]*sa1*sb0, (float)acc[mt][nt][3]*sa1*sb1);
        }
    }
}

// ---------------- quantize Wv rows -> int8 + per-row scale ----------------
__global__ void __launch_bounds__(256)
wvq8_kernel(const float* __restrict__ wv, int8_t* __restrict__ q, float* __restrict__ scale)
{
    __shared__ float red[256];
    const int row = blockIdx.x;          // P*CC
    const int tid = threadIdx.x;
    const float4* src = reinterpret_cast<const float4*>(wv + (size_t)row * CC);
    float4 v0 = src[2*tid], v1 = src[2*tid + 1];
    float mx = fmaxf(fmaxf(fabsf(v0.x), fabsf(v0.y)), fmaxf(fabsf(v0.z), fabsf(v0.w)));
    mx = fmaxf(mx, fmaxf(fmaxf(fabsf(v1.x), fabsf(v1.y)), fmaxf(fabsf(v1.z), fabsf(v1.w))));
    red[tid] = mx;
    __syncthreads();
    for (int o = 128; o > 0; o >>= 1) {
        if (tid < o) red[tid] = fmaxf(red[tid], red[tid + o]);
        __syncthreads();
    }
    const float m = fmaxf(red[0], 1e-30f);
    const float inv = 127.f / m;
    if (tid == 0) scale[row] = m / 127.f;
    uint2 out;
    out.x = packs8(q8(v0.x,inv), q8(v0.y,inv), q8(v0.z,inv), q8(v0.w,inv));
    out.y = packs8(q8(v1.x,inv), q8(v1.y,inv), q8(v1.z,inv), q8(v1.w,inv));
    reinterpret_cast<uint2*>(q + (size_t)row * CC)[tid] = out;
}

// ---------------- quantize xdT2 rows (bf16x2) -> int8 + per-row scale ----------------
__global__ void __launch_bounds__(256)
xdq8_kernel(const uint32_t* __restrict__ xdT2, int8_t* __restrict__ q, float* __restrict__ scale)
{
    __shared__ float red[256];
    const int row = blockIdx.x;          // P*BN3
    const int tid = threadIdx.x;
    const uint4 w = reinterpret_cast<const uint4*>(xdT2 + (size_t)row * CCW)[tid];
    float f[8];
    {
        __nv_bfloat162 b0 = *reinterpret_cast<const __nv_bfloat162*>(&w.x);
        __nv_bfloat162 b1 = *reinterpret_cast<const __nv_bfloat162*>(&w.y);
        __nv_bfloat162 b2 = *reinterpret_cast<const __nv_bfloat162*>(&w.z);
        __nv_bfloat162 b3 = *reinterpret_cast<const __nv_bfloat162*>(&w.w);
        f[0]=__bfloat162float(b0.x); f[1]=__bfloat162float(b0.y);
        f[2]=__bfloat162float(b1.x); f[3]=__bfloat162float(b1.y);
        f[4]=__bfloat162float(b2.x); f[5]=__bfloat162float(b2.y);
        f[6]=__bfloat162float(b3.x); f[7]=__bfloat162float(b3.y);
    }
    float mx = 0.f;
    #pragma unroll
    for (int i = 0; i < 8; i++) mx = fmaxf(mx, fabsf(f[i]));
    red[tid] = mx;
    __syncthreads();
    for (int o = 128; o > 0; o >>= 1) {
        if (tid < o) red[tid] = fmaxf(red[tid], red[tid + o]);
        __syncthreads();
    }
    const float m = fmaxf(red[0], 1e-30f);
    const float inv = 127.f / m;
    if (tid == 0) scale[row] = m / 127.f;
    uint2 out;
    out.x = packs8(q8(f[0],inv), q8(f[1],inv), q8(f[2],inv), q8(f[3],inv));
    out.y = packs8(q8(f[4],inv), q8(f[5],inv), q8(f[6],inv), q8(f[7],inv));
    reinterpret_cast<uint2*>(q + (size_t)row * CC)[tid] = out;
}

// ---------------- fused pool + packed transpose + xd row sums ----------------
__global__ void __launch_bounds__(256)
pool2_kernel(const float* __restrict__ x, uint32_t* __restrict__ xdT2, float* __restrict__ xsum)
{
    __shared__ float xs[32*97];
    const int c0 = blockIdx.x * 32, b = blockIdx.y, p = blockIdx.z;
    const int tid = threadIdx.x;
    #pragma unroll
    for (int it = 0; it < 12; it++) {
        int idx = it*256 + tid;
        int cr = idx / 96, n = idx % 96;
        int hd = n / 12, wd = n % 12;
        const float* bx = x + ((size_t)(b*CC + c0 + cr)*HH + p*PHH + 2*hd)*WW + 2*wd;
        float2 r0 = *reinterpret_cast<const float2*>(bx);
        float2 r1 = *reinterpret_cast<const float2*>(bx + WW);
        xs[cr*97 + n] = (r0.x + r0.y + r1.x + r1.y) * 0.25f;
    }
    __syncthreads();
    #pragma unroll
    for (int it = 0; it < 6; it++) {
        int idx = it*256 + tid;
        int w = idx & 15, n = idx >> 4;
        xdT2[((size_t)p*BN3 + b*NN + n)*CCW + (c0 >> 1) + w] =
            pack_bf2(xs[(2*w)*97 + n], xs[(2*w+1)*97 + n]);
    }
    if (tid < 32) {
        float s = 0.f;
        #pragma unroll
        for (int n = 0; n < NN; n++) s += xs[tid*97 + n];
        xsum[((size_t)(p*CC + c0 + tid))*BB + b] = s;
    }
}

// ============================================================================
// aoatt: ao[c,i] = sum_j u[c,j]*attn[i,j] + vb[c], fused GAP epilogue.
// ============================================================================
#define AO_STR 52
__global__ void __launch_bounds__(128)
aoatt_kernel(const uint32_t* __restrict__ u2, const uint32_t* __restrict__ attn2,
             const float* __restrict__ vb, const float* __restrict__ pa_gamma,
             const float* __restrict__ xsum, float* __restrict__ ao, float* __restrict__ gap)
{
    __shared__ uint32_t sU[128*AO_STR];
    __shared__ uint32_t sA[96*AO_STR];
    const int c0 = blockIdx.x * 128, b = blockIdx.y, p = blockIdx.z;
    const int tid = threadIdx.x;
    const int lane = tid & 31, warp = tid >> 5;
    const int wm = warp * 32;

    const uint32_t* Up = u2 + (size_t)p*CC*BN3W + (size_t)c0*BN3W + b*48;
    for (int i = tid; i < 128*12; i += 128) {
        int r = i / 12, s = i % 12;
        cp16(smem_u32(&sU[r*AO_STR + s*4]), Up + (size_t)r*BN3W + s*4);
    }
    const uint32_t* Atp = attn2 + (size_t)(b*PP + p)*NN*48;
    for (int i = tid; i < 96*12; i += 128) {
        int r = i / 12, s = i % 12;
        cp16(smem_u32(&sA[r*AO_STR + s*4]), Atp + r*48 + s*4);
    }
    CP_COMMIT(); CP_WAIT(0);
    __syncthreads();

    float acc[2][12][4];
    #pragma unroll
    for (int mt=0; mt<2; mt++)
        #pragma unroll
        for (int nt=0; nt<12; nt++)
            #pragma unroll
            for (int r=0; r<4; r++) acc[mt][nt][r] = 0.f;

    const uint32_t aL = smem_u32(sU) + (wm + (lane & 15))*AO_STR*4 + (lane >> 4)*16;
    const uint32_t bL = smem_u32(sA) + (((lane >> 4) << 3) + (lane & 7))*AO_STR*4
                        + ((lane >> 3) & 1)*16;
    #pragma unroll
    for (int k = 0; k < 6; k++) {
        uint32_t a[2][4], bq[6][4];
        #pragma unroll
        for (int mt = 0; mt < 2; mt++)
            ldsm4(a[mt], aL + mt*16*AO_STR*4 + k*32);
        #pragma unroll
        for (int ntp = 0; ntp < 6; ntp++)
            ldsm4(bq[ntp], bL + ntp*16*AO_STR*4 + k*32);
        #pragma unroll
        for (int mt = 0; mt < 2; mt++)
            #pragma unroll
            for (int ntp = 0; ntp < 6; ntp++) {
                mma_bf16(acc[mt][2*ntp],   a[mt], bq[ntp][0], bq[ntp][1]);
                mma_bf16(acc[mt][2*ntp+1], a[mt], bq[ntp][2], bq[ntp][3]);
            }
    }

    const int g = lane >> 2, t = lane & 3;
    const float gma = pa_gamma[p];
    float* aoP = ao + (size_t)(p*CC + c0)*BN3 + b*NN;
    #pragma unroll
    for (int mt = 0; mt < 2; mt++) {
        const int r0 = wm + mt*16 + g;
        const float bv0 = vb[p*CC + c0 + r0], bv1 = vb[p*CC + c0 + r0 + 8];
        float sa0 = 0.f, sa1 = 0.f;
        #pragma unroll
        for (int nt = 0; nt < 12; nt++) {
            const int col = nt*8 + 2*t;
            float v0 = acc[mt][nt][0] + bv0, v1 = acc[mt][nt][1] + bv0;
            float v2 = acc[mt][nt][2] + bv1, v3 = acc[mt][nt][3] + bv1;
            *reinterpret_cast<float2*>(aoP + (size_t)r0*BN3 + col)     = make_float2(v0, v1);
            *reinterpret_cast<float2*>(aoP + (size_t)(r0+8)*BN3 + col) = make_float2(v2, v3);
            sa0 += v0 + v1; sa1 += v2 + v3;
        }
        sa0 += __shfl_xor_sync(0xffffffffu, sa0, 1);
        sa0 += __shfl_xor_sync(0xffffffffu, sa0, 2);
        sa1 += __shfl_xor_sync(0xffffffffu, sa1, 1);
        sa1 += __shfl_xor_sync(0xffffffffu, sa1, 2);
        if (t == 0) {
            size_t i0 = (size_t)(p*CC + c0 + r0)*BB + b;
            size_t i1 = (size_t)(p*CC + c0 + r0 + 8)*BB + b;
            gap[i0] = (gma*sa0 + xsum[i0]) * (1.f/96.f);
            gap[i1] = (gma*sa1 + xsum[i1]) * (1.f/96.f);
        }
    }
}

// ---------------- generic small SGEMM (SE block only) ----------------
template<int BM,int BN,int BK,int TM,int TN,int EPI>
__global__ void __launch_bounds__((BM/TM)*(BN/TN))
sgemm_k(const float* __restrict__ A, const float* __restrict__ B,
        float* __restrict__ C, const float* __restrict__ bias,
        int M, int N, int K, long long sA, long long sB, long long sC, int sBias)
{
    constexpr int THREADS = (BM/TM)*(BN/TN);
    constexpr int TN2 = TN/2;
    __shared__ float As[BK][BM];
    __shared__ float Bs[BK][BN];
    const int p = blockIdx.z;
    A += (long long)p * sA;
    B += (long long)p * sB;
    C += (long long)p * sC;
    const float* bp = bias + (long long)p * sBias;
    const int bm = blockIdx.y * BM, bn = blockIdx.x * BN;
    const int tid = threadIdx.x;
    const int tcol = tid % (BN/TN);
    const int trow = tid / (BN/TN);

    unsigned long long acc[TM][TN2];
    #pragma unroll
    for (int i=0;i<TM;i++)
        #pragma unroll
        for (int j=0;j<TN2;j++) acc[i][j] = 0ull;

    for (int k0 = 0; k0 < K; k0 += BK) {
        #pragma unroll
        for (int i = tid; i < BM*BK; i += THREADS) {
            int r = i / BK, c = i % BK;
            As[c][r] = A[(long long)(bm + r) * K + k0 + c];
        }
        #pragma unroll
        for (int i = tid; i < BK*BN; i += THREADS) {
            int r = i / BN, c = i % BN;
            Bs[r][c] = B[(long long)(k0 + r) * N + bn + c];
        }
        __syncthreads();
        #pragma unroll
        for (int kk = 0; kk < BK; kk++) {
            unsigned long long av[TM], bv[TN2];
            #pragma unroll
            for (int i=0;i<TM;i++){ float a = As[kk][trow*TM + i]; av[i] = pk2(a, a); }
            const float2* brow = reinterpret_cast<const float2*>(&Bs[kk][tcol*TN]);
            #pragma unroll
            for (int j=0;j<TN2;j++){ float2 b2 = brow[j]; bv[j] = pk2(b2.x, b2.y); }
            #pragma unroll
            for (int i=0;i<TM;i++)
                #pragma unroll
                for (int j=0;j<TN2;j++)
                    acc[i][j] = ffma2(av[i], bv[j], acc[i][j]);
        }
        __syncthreads();
    }

    #pragma unroll
    for (int i=0;i<TM;i++) {
        int m = bm + trow*TM + i;
        float bvl = bp[m];
        #pragma unroll
        for (int j=0;j<TN2;j++) {
            float2 v = upk2(acc[i][j]);
            float v0 = v.x + bvl, v1 = v.y + bvl;
            if (EPI == 1) { v0 = v0 > 0.f ? v0 : 0.f; v1 = v1 > 0.f ? v1 : 0.f; }
            if (EPI == 2) { v0 = 1.f/(1.f+expf(-v0)); v1 = 1.f/(1.f+expf(-v1)); }
            int n = bn + tcol*TN + 2*j;
            C[(long long)m * N + n]     = v0;
            C[(long long)m * N + n + 1] = v1;
        }
    }
}

// ---------------- prep: fused q/k weights -> bf16x2 ----------------
__global__ void __launch_bounds__(256)
wqk_kernel(const float* __restrict__ pa_q_w, const float* __restrict__ pa_dw_q_w,
           const float* __restrict__ pa_k_w, const float* __restrict__ pa_dw_k_w,
           uint32_t* __restrict__ wqk2)
{
    int idx = blockIdx.x * 256 + threadIdx.x;
    if (idx >= PP*256*CCW) return;
    int w = idx & (CCW-1);
    int r = idx >> 10;
    int i = r % 256, p = r / 256;
    int c = 2*w;
    float v0, v1;
    if (i < ICC) {
        const float* W = pa_q_w + ((long long)p*ICC + i)*CC;
        const float* D = pa_dw_q_w + p*CC;
        v0 = W[c]*D[c]; v1 = W[c+1]*D[c+1];
    } else {
        const float* W = pa_k_w + ((long long)p*ICC + (i-ICC))*CC;
        const float* D = pa_dw_k_w + p*CC;
        v0 = W[c]*D[c]; v1 = W[c+1]*D[c+1];
    }
    wqk2[idx] = pack_bf2(v0, v1);
}

// ---------------- prep: fused q/k biases ----------------
__global__ void __launch_bounds__(256)
qkb_kernel(const float* __restrict__ pa_q_w, const float* __restrict__ pa_dw_q_b, const float* __restrict__ pa_q_b,
           const float* __restrict__ pa_k_w, const float* __restrict__ pa_dw_k_b, const float* __restrict__ pa_k_b,
           float* __restrict__ qkb)
{
    int w = blockIdx.x * 8 + threadIdx.x / 32;
    int lane = threadIdx.x & 31;
    if (w >= PP*256) return;
    int i = w % 256, p = w / 256;
    const float* Wp; const float* db; float base;
    if (i < ICC) { Wp = pa_q_w + ((long long)p*ICC + i)*CC; db = pa_dw_q_b + p*CC; base = pa_q_b[p*ICC + i]; }
    else         { Wp = pa_k_w + ((long long)p*ICC + (i-ICC))*CC; db = pa_dw_k_b + p*CC; base = pa_k_b[p*ICC + (i-ICC)]; }
    float s = 0.f;
    for (int c = lane; c < CC; c += 32) s += Wp[c] * db[c];
    #pragma unroll
    for (int o = 16; o > 0; o >>= 1) s += __shfl_xor_sync(0xffffffffu, s, o);
    if (lane == 0) qkb[w] = base + s;
}

// ---------------- prep: modality gate ----------------
__global__ void mw_kernel(const int* __restrict__ modality, const float* __restrict__ gw1,
                          const float* __restrict__ gb1, const float* __restrict__ gw2,
                          const float* __restrict__ gb2, float* __restrict__ mw)
{
    int t = threadIdx.x;
    if (t >= BB*PP) return;
    int b = t / PP, p = t % PP;
    float mf = (float)modality[b];
    float s = gb2[p];
    #pragma unroll
    for (int j = 0; j < 12; j++) {
        float g = mf * gw1[j] + gb1[j];
        g = g > 0.f ? g : 0.f;
        s += g * gw2[p*12 + j];
    }
    mw[t] = 1.f / (1.f + expf(-s));
}

// ---------------- energy + softmax -> packed attn2[i][j/2] ----------------
__global__ void __launch_bounds__(256)
attn_kernel(const float* __restrict__ qk, uint32_t* __restrict__ attn2)
{
    extern __shared__ float sm[];
    float* qs = sm;              // 128*96
    float* ks = sm + ICC*NN;     // 128*96
    const int bp = blockIdx.x;   // b*P + p
    const int b = bp / PP, p = bp % PP;
    const int tid = threadIdx.x;
    const float* qbase = qk + (long long)p*256*BN3 + b*NN;
    for (int i = tid; i < ICC*NN; i += 256) {
        int r = i / NN, n = i % NN;
        qs[i] = qbase[(long long)r*BN3 + n];
        ks[i] = qbase[(long long)(ICC + r)*BN3 + n];
    }
    __syncthreads();
    const int tn0 = (tid % 16) * 6, tm0 = (tid / 16) * 6;
    float acc[6][6] = {};
    for (int i = 0; i < ICC; i++) {
        float qf[6], kf[6];
        #pragma unroll
        for (int a=0;a<6;a++){ qf[a]=qs[i*NN+tn0+a]; kf[a]=ks[i*NN+tm0+a]; }
        #pragma unroll
        for (int a=0;a<6;a++)
            #pragma unroll
            for (int m=0;m<6;m++) acc[a][m] = fmaf(qf[a], kf[m], acc[a][m]);
    }
    __syncthreads();
    float* es = sm;              // reuse as 96x96 energy: es[i][j]
    #pragma unroll
    for (int a=0;a<6;a++)
        #pragma unroll
        for (int m=0;m<6;m++) es[(tn0+a)*NN + tm0+m] = acc[a][m];
    __syncthreads();
    const int warp = tid / 32, lane = tid & 31;
    for (int n = warp; n < NN; n += 8) {
        float v0 = es[n*NN + lane], v1 = es[n*NN + 32 + lane], v2 = es[n*NN + 64 + lane];
        float mx = fmaxf(v0, fmaxf(v1, v2));
        #pragma unroll
        for (int o=16;o>0;o>>=1) mx = fmaxf(mx, __shfl_xor_sync(0xffffffffu, mx, o));
        v0 = expf(v0 - mx); v1 = expf(v1 - mx); v2 = expf(v2 - mx);
        float s = v0 + v1 + v2;
        #pragma unroll
        for (int o=16;o>0;o>>=1) s += __shfl_xor_sync(0xffffffffu, s, o);
        float inv = 1.f / s;
        es[n*NN + lane]      = v0 * inv;
        es[n*NN + 32 + lane] = v1 * inv;
        es[n*NN + 64 + lane] = v2 * inv;
    }
    __syncthreads();
    uint32_t* dst = attn2 + (size_t)bp * NN * 48;
    for (int idx = tid; idx < NN*48; idx += 256) {
        int n = idx / 48, w = idx % 48;
        dst[idx] = pack_bf2(es[n*NN + 2*w], es[n*NN + 2*w + 1]);
    }
}

// ---------------- fused final ----------------
__global__ void __launch_bounds__(384)
final_kernel(const float* __restrict__ x, const float* __restrict__ ao,
             const float* __restrict__ cw, const float* __restrict__ mw,
             const float* __restrict__ pa_gamma, const float* __restrict__ ca_gamma,
             float* __restrict__ out)
{
    __shared__ float as_[NN];
    const int c = blockIdx.x;
    const int bp = blockIdx.y;
    const int b = bp / PP, p = bp % PP;
    const int tid = threadIdx.x;
    if (tid < NN) as_[tid] = ao[(long long)(p*CC + c)*BN3 + b*NN + tid];
    __syncthreads();
    const int y = tid / WW, xw = tid % WW;
    int ky = y >> 1, kx = xw >> 1;
    int y0, y1, x0, x1; float wy0, wy1, wx0, wx1;
    if ((y & 1) == 0) { y0 = ky > 0 ? ky-1 : 0; y1 = ky; wy0 = 0.25f; wy1 = 0.75f; }
    else              { y0 = ky; y1 = ky < HD-1 ? ky+1 : HD-1; wy0 = 0.75f; wy1 = 0.25f; }
    if ((xw & 1) == 0){ x0 = kx > 0 ? kx-1 : 0; x1 = kx; wx0 = 0.25f; wx1 = 0.75f; }
    else              { x0 = kx; x1 = kx < WD-1 ? kx+1 : WD-1; wx0 = 0.75f; wx1 = 0.25f; }
    float up = wy0*(wx0*as_[y0*WD + x0] + wx1*as_[y0*WD + x1])
             + wy1*(wx0*as_[y1*WD + x0] + wx1*as_[y1*WD + x1]);
    long long xi = ((long long)(b*CC + c)*HH + p*PHH + y)*WW + xw;
    float xpv = x[xi];
    float pa  = pa_gamma[p]*up + xpv;
    float cwv = cw[(long long)(p*CC + c)*BB + b];
    float ca  = ca_gamma[p]*(pa*cwv) + pa;
    float w   = mw[b*PP + p];
    out[xi] = xpv*(1.f - w) + ca*w;
}

// ---------------- launcher ----------------
extern "C" void kernel_launch(void* const* d_in, const int* in_sizes, int n_in,
                              void* d_out, int out_size)
{
    const float* x          = (const float*)d_in[0];
    const float* pa_dw_q_w  = (const float*)d_in[1];
    const float* pa_dw_q_b  = (const float*)d_in[2];
    const float* pa_q_w     = (const float*)d_in[3];
    const float* pa_q_b     = (const float*)d_in[4];
    const float* pa_dw_k_w  = (const float*)d_in[5];
    const float* pa_dw_k_b  = (const float*)d_in[6];
    const float* pa_k_w     = (const float*)d_in[7];
    const float* pa_k_b     = (const float*)d_in[8];
    const float* pa_v_w     = (const float*)d_in[9];
    const float* pa_v_b     = (const float*)d_in[10];
    const float* pa_gamma   = (const float*)d_in[11];
    const float* ca_fc1_w   = (const float*)d_in[12];
    const float* ca_fc1_b   = (const float*)d_in[13];
    const float* ca_fc2_w   = (const float*)d_in[14];
    const float* ca_fc2_b   = (const float*)d_in[15];
    const float* ca_gamma   = (const float*)d_in[16];
    const float* gate_w1    = (const float*)d_in[17];
    const float* gate_b1    = (const float*)d_in[18];
    const float* gate_w2    = (const float*)d_in[19];
    const float* gate_b2    = (const float*)d_in[20];
    const int*   modality   = (const int*)d_in[21];
    float* out = (float*)d_out;

    float *g_ao, *g_qk, *g_qkb, *g_xsum, *g_gap, *g_h1, *g_cw, *g_mw, *g_sWv, *g_sXd;
    uint32_t *g_xdT2, *g_u2, *g_wqk2, *g_attn2;
    int8_t *g_wq8, *g_xq8;
    cudaGetSymbolAddress((void**)&g_xdT2, d_xdT2);
    cudaGetSymbolAddress((void**)&g_xq8, d_xq8);
    cudaGetSymbolAddress((void**)&g_wq8, d_wq8);
    cudaGetSymbolAddress((void**)&g_sXd, d_sXd);
    cudaGetSymbolAddress((void**)&g_sWv, d_sWv);
    cudaGetSymbolAddress((void**)&g_u2, d_u2);
    cudaGetSymbolAddress((void**)&g_ao, d_ao);
    cudaGetSymbolAddress((void**)&g_qk, d_qk);
    cudaGetSymbolAddress((void**)&g_wqk2, d_wqk2);
    cudaGetSymbolAddress((void**)&g_qkb, d_qkb);
    cudaGetSymbolAddress((void**)&g_attn2, d_attn2);
    cudaGetSymbolAddress((void**)&g_xsum, d_xsum);
    cudaGetSymbolAddress((void**)&g_gap, d_gap);
    cudaGetSymbolAddress((void**)&g_h1, d_h1);
    cudaGetSymbolAddress((void**)&g_cw, d_cw);
    cudaGetSymbolAddress((void**)&g_mw, d_mw);

    cudaFuncSetAttribute(attn_kernel, cudaFuncAttributeMaxDynamicSharedMemorySize, 2*ICC*NN*4);
    cudaFuncSetAttribute(bmma_gemm, cudaFuncAttributeMaxDynamicSharedMemorySize, BG_SMEM);
    cudaFuncSetAttribute(imma_gemm, cudaFuncAttributeMaxDynamicSharedMemorySize, BG_SMEM);

    // prep
    wqk_kernel<<<(PP*256*CCW)/256, 256>>>(pa_q_w, pa_dw_q_w, pa_k_w, pa_dw_k_w, g_wqk2);
    qkb_kernel<<<(PP*256)/8, 256>>>(pa_q_w, pa_dw_q_b, pa_q_b, pa_k_w, pa_dw_k_b, pa_k_b, g_qkb);
    mw_kernel<<<1, 128>>>(modality, gate_w1, gate_b1, gate_w2, gate_b2, g_mw);
    wvq8_kernel<<<PP*CC, 256>>>(pa_v_w, g_wq8, g_sWv);

    // fused pool + packed transpose + xd row sums
    pool2_kernel<<<dim3(CC/32, BB, PP), 256>>>(x, g_xdT2, g_xsum);
    // quantize xd tokens
    xdq8_kernel<<<PP*BN3, 256>>>(g_xdT2, g_xq8, g_sXd);

    // u = Wv @ xd  (int8 mma, M=2048, N=3072, K=2048, packed bf16x2 output)
    imma_gemm<<<dim3(BN3/128, CC/128, PP), 128, BG_SMEM>>>(
        g_wq8, g_xq8, g_sWv, g_sXd, g_u2);

    // qk = Wqk' @ xd + b'   (bf16 mma, M=256, N=3072, K=2048)
    bmma_gemm<<<dim3(BN3/128, 256/128, PP), 128, BG_SMEM>>>(
        g_wqk2, g_xdT2, g_qk, g_qkb, BN3, CCW,
        (long long)256*CCW, (long long)BN3*CCW, (long long)256*BN3, 256);

    // attention -> packed attn2
    attn_kernel<<<BB*PP, 256, 2*ICC*NN*4>>>(g_qk, g_attn2);

    // ao = u @ attnT + vb, fused GAP
    aoatt_kernel<<<dim3(CC/128, BB, PP), 128>>>(
        g_u2, g_attn2, pa_v_b, pa_gamma, g_xsum, g_ao, g_gap);

    // SE block
    sgemm_k<64,32,16,4,2,1><<<dim3(1, C4/64, PP), 256>>>(
        ca_fc1_w, g_gap, g_h1, ca_fc1_b, C4, BB, CC,
        (long long)C4*CC, (long long)CC*BB, (long long)C4*BB, C4);
    sgemm_k<64,32,16,4,2,2><<<dim3(1, CC/64, PP), 256>>>(
        ca_fc2_w, g_h1, g_cw, ca_fc2_b, CC, BB, C4,
        (long long)CC*C4, (long long)C4*BB, (long long)CC*BB, CC);

    // fused upsample + residual + SE + gate
    final_kernel<<<dim3(CC, BB*PP), 384>>>(x, g_ao, g_cw, g_mw, pa_gamma, ca_gamma, out);
}

// round 16
// speedup vs baseline: 1.7407x; 1.7407x over previous
#include <cuda_runtime.h>
#include <cuda_bf16.h>
#include <math.h>
#include <stdint.h>

// ---------------- problem constants ----------------
#define BB 32
#define CC 2048
#define CCW 1024    // CC/2 packed words
#define HH 48
#define WW 24
#define PP 3
#define ICC 128     // IC
#define C4 512
#define PHH 16
#define HD 8
#define WD 12
#define NN 96       // HD*WD
#define BN3 3072    // BB*NN
#define BN3W 1536   // BN3/2 packed words

// ---------------- scratch (device globals; no allocs allowed) ----------------
__device__ uint32_t d_xdT2 [(size_t)PP*BN3*CCW];  // (P,B*N,C/2) bf16x2
__device__ uint32_t d_u2   [(size_t)PP*CC*BN3W];  // (P,C,B*N/2) bf16x2 : u = Wv@xd
__device__ uint32_t d_ao2  [(size_t)PP*CC*BN3W];  // (P,C,B*N/2) bf16x2
__device__ float    d_qk   [(size_t)PP*256*BN3];  // (P,256,B*N)
__device__ uint32_t d_wqk2 [(size_t)PP*256*CCW];  // fused q/k weights bf16x2
__device__ uint32_t d_wv2  [(size_t)PP*CC*CCW];   // Wv bf16x2
__device__ float    d_qkb  [(size_t)PP*256];
__device__ uint32_t d_attn2[(size_t)BB*PP*NN*48]; // attn[i][j] bf16x2
__device__ float    d_xsum [(size_t)PP*CC*BB];
__device__ float    d_gap  [(size_t)PP*CC*BB];
__device__ float    d_h1   [(size_t)PP*C4*BB];
__device__ float    d_cw   [(size_t)PP*CC*BB];
__device__ float    d_mw   [BB*PP];

// ---------------- packed fp32x2 helpers ----------------
__device__ __forceinline__ unsigned long long pk2(float lo, float hi){
    unsigned long long r;
    asm("mov.b64 %0, {%1, %2};" : "=l"(r) : "f"(lo), "f"(hi));
    return r;
}
__device__ __forceinline__ unsigned long long ffma2(unsigned long long a, unsigned long long b, unsigned long long c){
    unsigned long long d;
    asm("fma.rn.f32x2 %0, %1, %2, %3;" : "=l"(d) : "l"(a), "l"(b), "l"(c));
    return d;
}
__device__ __forceinline__ float2 upk2(unsigned long long v){
    float2 f;
    asm("mov.b64 {%0, %1}, %2;" : "=f"(f.x), "=f"(f.y) : "l"(v));
    return f;
}

// ---------------- bf16 / mma helpers ----------------
__device__ __forceinline__ uint32_t pack_bf2(float lo, float hi){
    __nv_bfloat162 v = __float22bfloat162_rn(make_float2(lo, hi)); // .x -> low half
    return *reinterpret_cast<uint32_t*>(&v);
}
__device__ __forceinline__ void mma_bf16(float* c, const uint32_t* a, uint32_t b0, uint32_t b1){
    asm volatile("mma.sync.aligned.m16n8k16.row.col.f32.bf16.bf16.f32 "
        "{%0,%1,%2,%3}, {%4,%5,%6,%7}, {%8,%9}, {%0,%1,%2,%3};"
        : "+f"(c[0]), "+f"(c[1]), "+f"(c[2]), "+f"(c[3])
        : "r"(a[0]), "r"(a[1]), "r"(a[2]), "r"(a[3]), "r"(b0), "r"(b1));
}
__device__ __forceinline__ void ldsm4(uint32_t* r, uint32_t addr){
    asm volatile("ldmatrix.sync.aligned.m8n8.x4.shared.b16 {%0,%1,%2,%3}, [%4];"
        : "=r"(r[0]), "=r"(r[1]), "=r"(r[2]), "=r"(r[3]) : "r"(addr));
}
__device__ __forceinline__ uint32_t smem_u32(const void* p){
    uint32_t a;
    asm("{ .reg .u64 t; cvta.to.shared.u64 t, %1; cvt.u32.u64 %0, t; }" : "=r"(a) : "l"(p));
    return a;
}
__device__ __forceinline__ void cp16(uint32_t dst, const void* src){
    asm volatile("cp.async.cg.shared.global [%0], [%1], 16;" :: "r"(dst), "l"(src));
}
#define CP_COMMIT() asm volatile("cp.async.commit_group;" ::: "memory")
#define CP_WAIT(n)  asm volatile("cp.async.wait_group %0;" :: "n"(n) : "memory")

// ============================================================================
// bf16 mma.sync GEMM core (R13-validated): C[M,N] = sum_k A[m,k]*B[n,k]
// CTA tile 128x128, BK=64 bf16 (32 words), 128 threads, 3-stage cp.async.
// EPI 0: f32 +bias[m] output;  EPI 1: packed bf16x2 output, no bias.
// ============================================================================
#define BG_ROWB 144
#define BG_BOFF (128*BG_ROWB)
#define BG_STAGE (256*BG_ROWB)
#define BG_SMEM (3*BG_STAGE)

template<int EPI>
__global__ void __launch_bounds__(128, 2)
bmma_gemm(const uint32_t* __restrict__ A2, const uint32_t* __restrict__ B2,
          void* __restrict__ Cout, const float* __restrict__ bias,
          int N, int Kw, long long sA, long long sB, long long sC, int sBias)
{
    extern __shared__ float smf[];
    const uint32_t su = smem_u32(smf);
    const int tid = threadIdx.x;
    const int p = blockIdx.z;
    const int bm = blockIdx.y * 128, bn = blockIdx.x * 128;
    const uint32_t* Ap = A2 + (size_t)p * sA + (size_t)bm * Kw;
    const uint32_t* Bp = B2 + (size_t)p * sB + (size_t)bn * Kw;

    const int lane = tid & 31, warp = tid >> 5;
    const int wm = (warp & 1) * 64, wn = (warp >> 1) * 64;

    float acc[4][8][4];
    #pragma unroll
    for (int mt=0; mt<4; mt++)
        #pragma unroll
        for (int nt=0; nt<8; nt++)
            #pragma unroll
            for (int r=0; r<4; r++) acc[mt][nt][r] = 0.f;

    const int row0 = tid >> 3, seg = tid & 7;

    auto load = [&](int kw0, int s){
        const uint32_t base = su + s * BG_STAGE;
        #pragma unroll
        for (int i = 0; i < 8; i++)
            cp16(base + (row0 + i*16)*BG_ROWB + seg*16,
                 Ap + (size_t)(row0 + i*16)*Kw + kw0 + seg*4);
        #pragma unroll
        for (int i = 0; i < 8; i++)
            cp16(base + BG_BOFF + (row0 + i*16)*BG_ROWB + seg*16,
                 Bp + (size_t)(row0 + i*16)*Kw + kw0 + seg*4);
        CP_COMMIT();
    };

    const uint32_t aLane = su + (wm + (lane & 15))*BG_ROWB + (lane >> 4)*16;
    const uint32_t bLane = su + BG_BOFF + (wn + ((lane >> 4) << 3) + (lane & 7))*BG_ROWB
                              + ((lane >> 3) & 1)*16;

    const int nC = Kw / 32;
    load(0, 0);
    load(32, 1);
    for (int i = 0; i < nC; i++) {
        const int s = i % 3;
        if (i + 1 < nC) { CP_WAIT(1); } else { CP_WAIT(0); }
        __syncthreads();
        if (i + 2 < nC) load((i+2)*32, (i+2)%3);
        const uint32_t aS = aLane + s*BG_STAGE;
        const uint32_t bS = bLane + s*BG_STAGE;
        #pragma unroll
        for (int k = 0; k < 4; k++) {
            uint32_t a[4][4], bq[4][4];
            #pragma unroll
            for (int mt = 0; mt < 4; mt++)
                ldsm4(a[mt], aS + mt*16*BG_ROWB + k*32);
            #pragma unroll
            for (int ntp = 0; ntp < 4; ntp++)
                ldsm4(bq[ntp], bS + ntp*16*BG_ROWB + k*32);
            #pragma unroll
            for (int mt = 0; mt < 4; mt++)
                #pragma unroll
                for (int ntp = 0; ntp < 4; ntp++) {
                    mma_bf16(acc[mt][2*ntp],   a[mt], bq[ntp][0], bq[ntp][1]);
                    mma_bf16(acc[mt][2*ntp+1], a[mt], bq[ntp][2], bq[ntp][3]);
                }
        }
    }

    const int g = lane >> 2, t = lane & 3;
    if (EPI == 0) {
        const float* bp = bias + (size_t)p * sBias + bm;
        float* Cp = (float*)Cout + (size_t)p * sC + (size_t)bm * N + bn;
        #pragma unroll
        for (int mt = 0; mt < 4; mt++) {
            const int r0 = wm + mt*16 + g;
            const float bv0 = bp[r0], bv1 = bp[r0 + 8];
            #pragma unroll
            for (int nt = 0; nt < 8; nt++) {
                const int col = wn + nt*8 + 2*t;
                float2 v0 = make_float2(acc[mt][nt][0] + bv0, acc[mt][nt][1] + bv0);
                float2 v1 = make_float2(acc[mt][nt][2] + bv1, acc[mt][nt][3] + bv1);
                *reinterpret_cast<float2*>(Cp + (size_t)r0*N + col)     = v0;
                *reinterpret_cast<float2*>(Cp + (size_t)(r0+8)*N + col) = v1;
            }
        }
    } else {
        const int Nw = N >> 1;
        uint32_t* Cp = (uint32_t*)Cout + (size_t)p * sC + (size_t)bm * Nw + (bn >> 1);
        #pragma unroll
        for (int mt = 0; mt < 4; mt++) {
            const int r0 = wm + mt*16 + g;
            #pragma unroll
            for (int nt = 0; nt < 8; nt++) {
                const int colw = (wn + nt*8 + 2*t) >> 1;
                Cp[(size_t)r0*Nw + colw]     = pack_bf2(acc[mt][nt][0], acc[mt][nt][1]);
                Cp[(size_t)(r0+8)*Nw + colw] = pack_bf2(acc[mt][nt][2], acc[mt][nt][3]);
            }
        }
    }
}

// ---------------- f32 (float4) -> bf16x2 pairs ----------------
__global__ void __launch_bounds__(256)
conv_bf2_kernel(const float4* __restrict__ in, uint2* __restrict__ out, long long n4)
{
    long long i = (long long)blockIdx.x * 256 + threadIdx.x;
    if (i < n4) {
        float4 v = in[i];
        out[i] = make_uint2(pack_bf2(v.x, v.y), pack_bf2(v.z, v.w));
    }
}

// ---------------- fused pool + packed transpose + xd row sums ----------------
__global__ void __launch_bounds__(256)
pool2_kernel(const float* __restrict__ x, uint32_t* __restrict__ xdT2, float* __restrict__ xsum)
{
    __shared__ float xs[32*97];
    const int c0 = blockIdx.x * 32, b = blockIdx.y, p = blockIdx.z;
    const int tid = threadIdx.x;
    #pragma unroll
    for (int it = 0; it < 12; it++) {
        int idx = it*256 + tid;
        int cr = idx / 96, n = idx % 96;
        int hd = n / 12, wd = n % 12;
        const float* bx = x + ((size_t)(b*CC + c0 + cr)*HH + p*PHH + 2*hd)*WW + 2*wd;
        float2 r0 = *reinterpret_cast<const float2*>(bx);
        float2 r1 = *reinterpret_cast<const float2*>(bx + WW);
        xs[cr*97 + n] = (r0.x + r0.y + r1.x + r1.y) * 0.25f;
    }
    __syncthreads();
    #pragma unroll
    for (int it = 0; it < 6; it++) {
        int idx = it*256 + tid;
        int w = idx & 15, n = idx >> 4;
        xdT2[((size_t)p*BN3 + b*NN + n)*CCW + (c0 >> 1) + w] =
            pack_bf2(xs[(2*w)*97 + n], xs[(2*w+1)*97 + n]);
    }
    if (tid < 32) {
        float s = 0.f;
        #pragma unroll
        for (int n = 0; n < NN; n++) s += xs[tid*97 + n];
        xsum[((size_t)(p*CC + c0 + tid))*BB + b] = s;
    }
}

// ============================================================================
// aoatt: ao[c,i] = sum_j u[c,j]*attn[i,j] + vb[c], fused GAP epilogue.
// ao written as packed bf16x2. GAP reduced in fp32 pre-pack.
// ============================================================================
#define AO_STR 52
__global__ void __launch_bounds__(128)
aoatt_kernel(const uint32_t* __restrict__ u2, const uint32_t* __restrict__ attn2,
             const float* __restrict__ vb, const float* __restrict__ pa_gamma,
             const float* __restrict__ xsum, uint32_t* __restrict__ ao2, float* __restrict__ gap)
{
    __shared__ uint32_t sU[128*AO_STR];
    __shared__ uint32_t sA[96*AO_STR];
    const int c0 = blockIdx.x * 128, b = blockIdx.y, p = blockIdx.z;
    const int tid = threadIdx.x;
    const int lane = tid & 31, warp = tid >> 5;
    const int wm = warp * 32;

    const uint32_t* Up = u2 + (size_t)p*CC*BN3W + (size_t)c0*BN3W + b*48;
    for (int i = tid; i < 128*12; i += 128) {
        int r = i / 12, s = i % 12;
        cp16(smem_u32(&sU[r*AO_STR + s*4]), Up + (size_t)r*BN3W + s*4);
    }
    const uint32_t* Atp = attn2 + (size_t)(b*PP + p)*NN*48;
    for (int i = tid; i < 96*12; i += 128) {
        int r = i / 12, s = i % 12;
        cp16(smem_u32(&sA[r*AO_STR + s*4]), Atp + r*48 + s*4);
    }
    CP_COMMIT(); CP_WAIT(0);
    __syncthreads();

    float acc[2][12][4];
    #pragma unroll
    for (int mt=0; mt<2; mt++)
        #pragma unroll
        for (int nt=0; nt<12; nt++)
            #pragma unroll
            for (int r=0; r<4; r++) acc[mt][nt][r] = 0.f;

    const uint32_t aL = smem_u32(sU) + (wm + (lane & 15))*AO_STR*4 + (lane >> 4)*16;
    const uint32_t bL = smem_u32(sA) + (((lane >> 4) << 3) + (lane & 7))*AO_STR*4
                        + ((lane >> 3) & 1)*16;
    #pragma unroll
    for (int k = 0; k < 6; k++) {
        uint32_t a[2][4], bq[6][4];
        #pragma unroll
        for (int mt = 0; mt < 2; mt++)
            ldsm4(a[mt], aL + mt*16*AO_STR*4 + k*32);
        #pragma unroll
        for (int ntp = 0; ntp < 6; ntp++)
            ldsm4(bq[ntp], bL + ntp*16*AO_STR*4 + k*32);
        #pragma unroll
        for (int mt = 0; mt < 2; mt++)
            #pragma unroll
            for (int ntp = 0; ntp < 6; ntp++) {
                mma_bf16(acc[mt][2*ntp],   a[mt], bq[ntp][0], bq[ntp][1]);
                mma_bf16(acc[mt][2*ntp+1], a[mt], bq[ntp][2], bq[ntp][3]);
            }
    }

    const int g = lane >> 2, t = lane & 3;
    const float gma = pa_gamma[p];
    uint32_t* aoP = ao2 + (size_t)(p*CC + c0)*BN3W + b*48;
    #pragma unroll
    for (int mt = 0; mt < 2; mt++) {
        const int r0 = wm + mt*16 + g;
        const float bv0 = vb[p*CC + c0 + r0], bv1 = vb[p*CC + c0 + r0 + 8];
        float sa0 = 0.f, sa1 = 0.f;
        #pragma unroll
        for (int nt = 0; nt < 12; nt++) {
            const int colw = nt*4 + t;
            float v0 = acc[mt][nt][0] + bv0, v1 = acc[mt][nt][1] + bv0;
            float v2 = acc[mt][nt][2] + bv1, v3 = acc[mt][nt][3] + bv1;
            aoP[(size_t)r0*BN3W + colw]     = pack_bf2(v0, v1);
            aoP[(size_t)(r0+8)*BN3W + colw] = pack_bf2(v2, v3);
            sa0 += v0 + v1; sa1 += v2 + v3;
        }
        sa0 += __shfl_xor_sync(0xffffffffu, sa0, 1);
        sa0 += __shfl_xor_sync(0xffffffffu, sa0, 2);
        sa1 += __shfl_xor_sync(0xffffffffu, sa1, 1);
        sa1 += __shfl_xor_sync(0xffffffffu, sa1, 2);
        if (t == 0) {
            size_t i0 = (size_t)(p*CC + c0 + r0)*BB + b;
            size_t i1 = (size_t)(p*CC + c0 + r0 + 8)*BB + b;
            gap[i0] = (gma*sa0 + xsum[i0]) * (1.f/96.f);
            gap[i1] = (gma*sa1 + xsum[i1]) * (1.f/96.f);
        }
    }
}

// ---------------- generic small SGEMM (SE block only) ----------------
template<int BM,int BN,int BK,int TM,int TN,int EPI>
__global__ void __launch_bounds__((BM/TM)*(BN/TN))
sgemm_k(const float* __restrict__ A, const float* __restrict__ B,
        float* __restrict__ C, const float* __restrict__ bias,
        int M, int N, int K, long long sA, long long sB, long long sC, int sBias)
{
    constexpr int THREADS = (BM/TM)*(BN/TN);
    constexpr int TN2 = TN/2;
    __shared__ float As[BK][BM];
    __shared__ float Bs[BK][BN];
    const int p = blockIdx.z;
    A += (long long)p * sA;
    B += (long long)p * sB;
    C += (long long)p * sC;
    const float* bp = bias + (long long)p * sBias;
    const int bm = blockIdx.y * BM, bn = blockIdx.x * BN;
    const int tid = threadIdx.x;
    const int tcol = tid % (BN/TN);
    const int trow = tid / (BN/TN);

    unsigned long long acc[TM][TN2];
    #pragma unroll
    for (int i=0;i<TM;i++)
        #pragma unroll
        for (int j=0;j<TN2;j++) acc[i][j] = 0ull;

    for (int k0 = 0; k0 < K; k0 += BK) {
        #pragma unroll
        for (int i = tid; i < BM*BK; i += THREADS) {
            int r = i / BK, c = i % BK;
            As[c][r] = A[(long long)(bm + r) * K + k0 + c];
        }
        #pragma unroll
        for (int i = tid; i < BK*BN; i += THREADS) {
            int r = i / BN, c = i % BN;
            Bs[r][c] = B[(long long)(k0 + r) * N + bn + c];
        }
        __syncthreads();
        #pragma unroll
        for (int kk = 0; kk < BK; kk++) {
            unsigned long long av[TM], bv[TN2];
            #pragma unroll
            for (int i=0;i<TM;i++){ float a = As[kk][trow*TM + i]; av[i] = pk2(a, a); }
            const float2* brow = reinterpret_cast<const float2*>(&Bs[kk][tcol*TN]);
            #pragma unroll
            for (int j=0;j<TN2;j++){ float2 b2 = brow[j]; bv[j] = pk2(b2.x, b2.y); }
            #pragma unroll
            for (int i=0;i<TM;i++)
                #pragma unroll
                for (int j=0;j<TN2;j++)
                    acc[i][j] = ffma2(av[i], bv[j], acc[i][j]);
        }
        __syncthreads();
    }

    #pragma unroll
    for (int i=0;i<TM;i++) {
        int m = bm + trow*TM + i;
        float bvl = bp[m];
        #pragma unroll
        for (int j=0;j<TN2;j++) {
            float2 v = upk2(acc[i][j]);
            float v0 = v.x + bvl, v1 = v.y + bvl;
            if (EPI == 1) { v0 = v0 > 0.f ? v0 : 0.f; v1 = v1 > 0.f ? v1 : 0.f; }
            if (EPI == 2) { v0 = 1.f/(1.f+expf(-v0)); v1 = 1.f/(1.f+expf(-v1)); }
            int n = bn + tcol*TN + 2*j;
            C[(long long)m * N + n]     = v0;
            C[(long long)m * N + n + 1] = v1;
        }
    }
}

// ---------------- prep: fused q/k weights -> bf16x2 ----------------
__global__ void __launch_bounds__(256)
wqk_kernel(const float* __restrict__ pa_q_w, const float* __restrict__ pa_dw_q_w,
           const float* __restrict__ pa_k_w, const float* __restrict__ pa_dw_k_w,
           uint32_t* __restrict__ wqk2)
{
    int idx = blockIdx.x * 256 + threadIdx.x;
    if (idx >= PP*256*CCW) return;
    int w = idx & (CCW-1);
    int r = idx >> 10;
    int i = r % 256, p = r / 256;
    int c = 2*w;
    float v0, v1;
    if (i < ICC) {
        const float* W = pa_q_w + ((long long)p*ICC + i)*CC;
        const float* D = pa_dw_q_w + p*CC;
        v0 = W[c]*D[c]; v1 = W[c+1]*D[c+1];
    } else {
        const float* W = pa_k_w + ((long long)p*ICC + (i-ICC))*CC;
        const float* D = pa_dw_k_w + p*CC;
        v0 = W[c]*D[c]; v1 = W[c+1]*D[c+1];
    }
    wqk2[idx] = pack_bf2(v0, v1);
}

// ---------------- prep: fused q/k biases ----------------
__global__ void __launch_bounds__(256)
qkb_kernel(const float* __restrict__ pa_q_w, const float* __restrict__ pa_dw_q_b, const float* __restrict__ pa_q_b,
           const float* __restrict__ pa_k_w, const float* __restrict__ pa_dw_k_b, const float* __restrict__ pa_k_b,
           float* __restrict__ qkb)
{
    int w = blockIdx.x * 8 + threadIdx.x / 32;
    int lane = threadIdx.x & 31;
    if (w >= PP*256) return;
    int i = w % 256, p = w / 256;
    const float* Wp; const float* db; float base;
    if (i < ICC) { Wp = pa_q_w + ((long long)p*ICC + i)*CC; db = pa_dw_q_b + p*CC; base = pa_q_b[p*ICC + i]; }
    else         { Wp = pa_k_w + ((long long)p*ICC + (i-ICC))*CC; db = pa_dw_k_b + p*CC; base = pa_k_b[p*ICC + (i-ICC)]; }
    float s = 0.f;
    for (int c = lane; c < CC; c += 32) s += Wp[c] * db[c];
    #pragma unroll
    for (int o = 16; o > 0; o >>= 1) s += __shfl_xor_sync(0xffffffffu, s, o);
    if (lane == 0) qkb[w] = base + s;
}

// ---------------- prep: modality gate ----------------
__global__ void mw_kernel(const int* __restrict__ modality, const float* __restrict__ gw1,
                          const float* __restrict__ gb1, const float* __restrict__ gw2,
                          const float* __restrict__ gb2, float* __restrict__ mw)
{
    int t = threadIdx.x;
    if (t >= BB*PP) return;
    int b = t / PP, p = t % PP;
    float mf = (float)modality[b];
    float s = gb2[p];
    #pragma unroll
    for (int j = 0; j < 12; j++) {
        float g = mf * gw1[j] + gb1[j];
        g = g > 0.f ? g : 0.f;
        s += g * gw2[p*12 + j];
    }
    mw[t] = 1.f / (1.f + expf(-s));
}

// ---------------- energy + softmax -> packed attn2[i][j/2] ----------------
__global__ void __launch_bounds__(256)
attn_kernel(const float* __restrict__ qk, uint32_t* __restrict__ attn2)
{
    extern __shared__ float sm[];
    float* qs = sm;              // 128*96
    float* ks = sm + ICC*NN;     // 128*96
    const int bp = blockIdx.x;   // b*P + p
    const int b = bp / PP, p = bp % PP;
    const int tid = threadIdx.x;
    const float* qbase = qk + (long long)p*256*BN3 + b*NN;
    for (int i = tid; i < ICC*NN; i += 256) {
        int r = i / NN, n = i % NN;
        qs[i] = qbase[(long long)r*BN3 + n];
        ks[i] = qbase[(long long)(ICC + r)*BN3 + n];
    }
    __syncthreads();
    const int tn0 = (tid % 16) * 6, tm0 = (tid / 16) * 6;
    float acc[6][6] = {};
    for (int i = 0; i < ICC; i++) {
        float qf[6], kf[6];
        #pragma unroll
        for (int a=0;a<6;a++){ qf[a]=qs[i*NN+tn0+a]; kf[a]=ks[i*NN+tm0+a]; }
        #pragma unroll
        for (int a=0;a<6;a++)
            #pragma unroll
            for (int m=0;m<6;m++) acc[a][m] = fmaf(qf[a], kf[m], acc[a][m]);
    }
    __syncthreads();
    float* es = sm;              // reuse as 96x96 energy: es[i][j]
    #pragma unroll
    for (int a=0;a<6;a++)
        #pragma unroll
        for (int m=0;m<6;m++) es[(tn0+a)*NN + tm0+m] = acc[a][m];
    __syncthreads();
    const int warp = tid / 32, lane = tid & 31;
    for (int n = warp; n < NN; n += 8) {
        float v0 = es[n*NN + lane], v1 = es[n*NN + 32 + lane], v2 = es[n*NN + 64 + lane];
        float mx = fmaxf(v0, fmaxf(v1, v2));
        #pragma unroll
        for (int o=16;o>0;o>>=1) mx = fmaxf(mx, __shfl_xor_sync(0xffffffffu, mx, o));
        v0 = expf(v0 - mx); v1 = expf(v1 - mx); v2 = expf(v2 - mx);
        float s = v0 + v1 + v2;
        #pragma unroll
        for (int o=16;o>0;o>>=1) s += __shfl_xor_sync(0xffffffffu, s, o);
        float inv = 1.f / s;
        es[n*NN + lane]      = v0 * inv;
        es[n*NN + 32 + lane] = v1 * inv;
        es[n*NN + 64 + lane] = v2 * inv;
    }
    __syncthreads();
    uint32_t* dst = attn2 + (size_t)bp * NN * 48;
    for (int idx = tid; idx < NN*48; idx += 256) {
        int n = idx / 48, w = idx % 48;
        dst[idx] = pack_bf2(es[n*NN + 2*w], es[n*NN + 2*w + 1]);
    }
}

// ---------------- fused final (float4, 4 channels per block, ao in bf16x2) ----------------
__global__ void __launch_bounds__(384)
final_kernel(const float* __restrict__ x, const uint32_t* __restrict__ ao2,
             const float* __restrict__ cw, const float* __restrict__ mw,
             const float* __restrict__ pa_gamma, const float* __restrict__ ca_gamma,
             float* __restrict__ out)
{
    __shared__ float as_[4][97];
    const int c0 = blockIdx.x * 4;
    const int bp = blockIdx.y;
    const int b = bp / PP, p = bp % PP;
    const int tid = threadIdx.x;
    if (tid < 192) {
        int cl = tid / 48, w = tid % 48;
        uint32_t v = ao2[((size_t)(p*CC + c0 + cl))*BN3W + b*48 + w];
        __nv_bfloat162 bb = *reinterpret_cast<__nv_bfloat162*>(&v);
        as_[cl][2*w]     = __bfloat162float(bb.x);
        as_[cl][2*w + 1] = __bfloat162float(bb.y);
    }
    __syncthreads();
    const int cl = tid / 96, e4 = tid % 96;
    const int c = c0 + cl;
    const int y = e4 / 6, xw0 = (e4 % 6) * 4;
    const int ky = y >> 1;
    int y0, y1; float wy0, wy1;
    if ((y & 1) == 0) { y0 = ky > 0 ? ky-1 : 0; y1 = ky; wy0 = 0.25f; wy1 = 0.75f; }
    else              { y0 = ky; y1 = ky < HD-1 ? ky+1 : HD-1; wy0 = 0.75f; wy1 = 0.25f; }
    float up[4];
    #pragma unroll
    for (int l = 0; l < 4; l++) {
        int xw = xw0 + l;
        int kx = xw >> 1;
        int x0, x1; float wx0, wx1;
        if ((xw & 1) == 0){ x0 = kx > 0 ? kx-1 : 0; x1 = kx; wx0 = 0.25f; wx1 = 0.75f; }
        else              { x0 = kx; x1 = kx < WD-1 ? kx+1 : WD-1; wx0 = 0.75f; wx1 = 0.25f; }
        up[l] = wy0*(wx0*as_[cl][y0*WD + x0] + wx1*as_[cl][y0*WD + x1])
              + wy1*(wx0*as_[cl][y1*WD + x0] + wx1*as_[cl][y1*WD + x1]);
    }
    size_t xi = (((size_t)(b*CC + c))*HH + p*PHH + y)*WW + xw0;
    float4 xv = *reinterpret_cast<const float4*>(x + xi);
    const float cwv = cw[((size_t)(p*CC + c))*BB + b];
    const float gpa = pa_gamma[p], gca = ca_gamma[p], w = mw[b*PP + p];
    float xvv[4] = {xv.x, xv.y, xv.z, xv.w};
    float ov[4];
    #pragma unroll
    for (int l = 0; l < 4; l++) {
        float pa = gpa*up[l] + xvv[l];
        float ca = gca*(pa*cwv) + pa;
        ov[l] = xvv[l]*(1.f - w) + ca*w;
    }
    *reinterpret_cast<float4*>(out + xi) = make_float4(ov[0], ov[1], ov[2], ov[3]);
}

// ---------------- launcher ----------------
extern "C" void kernel_launch(void* const* d_in, const int* in_sizes, int n_in,
                              void* d_out, int out_size)
{
    const float* x          = (const float*)d_in[0];
    const float* pa_dw_q_w  = (const float*)d_in[1];
    const float* pa_dw_q_b  = (const float*)d_in[2];
    const float* pa_q_w     = (const float*)d_in[3];
    const float* pa_q_b     = (const float*)d_in[4];
    const float* pa_dw_k_w  = (const float*)d_in[5];
    const float* pa_dw_k_b  = (const float*)d_in[6];
    const float* pa_k_w     = (const float*)d_in[7];
    const float* pa_k_b     = (const float*)d_in[8];
    const float* pa_v_w     = (const float*)d_in[9];
    const float* pa_v_b     = (const float*)d_in[10];
    const float* pa_gamma   = (const float*)d_in[11];
    const float* ca_fc1_w   = (const float*)d_in[12];
    const float* ca_fc1_b   = (const float*)d_in[13];
    const float* ca_fc2_w   = (const float*)d_in[14];
    const float* ca_fc2_b   = (const float*)d_in[15];
    const float* ca_gamma   = (const float*)d_in[16];
    const float* gate_w1    = (const float*)d_in[17];
    const float* gate_b1    = (const float*)d_in[18];
    const float* gate_w2    = (const float*)d_in[19];
    const float* gate_b2    = (const float*)d_in[20];
    const int*   modality   = (const int*)d_in[21];
    float* out = (float*)d_out;

    float *g_qk, *g_qkb, *g_xsum, *g_gap, *g_h1, *g_cw, *g_mw;
    uint32_t *g_xdT2, *g_u2, *g_ao2, *g_wv2, *g_wqk2, *g_attn2;
    cudaGetSymbolAddress((void**)&g_xdT2, d_xdT2);
    cudaGetSymbolAddress((void**)&g_u2, d_u2);
    cudaGetSymbolAddress((void**)&g_ao2, d_ao2);
    cudaGetSymbolAddress((void**)&g_qk, d_qk);
    cudaGetSymbolAddress((void**)&g_wqk2, d_wqk2);
    cudaGetSymbolAddress((void**)&g_wv2, d_wv2);
    cudaGetSymbolAddress((void**)&g_qkb, d_qkb);
    cudaGetSymbolAddress((void**)&g_attn2, d_attn2);
    cudaGetSymbolAddress((void**)&g_xsum, d_xsum);
    cudaGetSymbolAddress((void**)&g_gap, d_gap);
    cudaGetSymbolAddress((void**)&g_h1, d_h1);
    cudaGetSymbolAddress((void**)&g_cw, d_cw);
    cudaGetSymbolAddress((void**)&g_mw, d_mw);

    cudaFuncSetAttribute(attn_kernel, cudaFuncAttributeMaxDynamicSharedMemorySize, 2*ICC*NN*4);
    cudaFuncSetAttribute(bmma_gemm<0>, cudaFuncAttributeMaxDynamicSharedMemorySize, BG_SMEM);
    cudaFuncSetAttribute(bmma_gemm<1>, cudaFuncAttributeMaxDynamicSharedMemorySize, BG_SMEM);

    // prep
    wqk_kernel<<<(PP*256*CCW)/256, 256>>>(pa_q_w, pa_dw_q_w, pa_k_w, pa_dw_k_w, g_wqk2);
    qkb_kernel<<<(PP*256)/8, 256>>>(pa_q_w, pa_dw_q_b, pa_q_b, pa_k_w, pa_dw_k_b, pa_k_b, g_qkb);
    mw_kernel<<<1, 128>>>(modality, gate_w1, gate_b1, gate_w2, gate_b2, g_mw);
    conv_bf2_kernel<<<(int)(((long long)PP*CC*CC/4 + 255)/256), 256>>>(
        (const float4*)pa_v_w, (uint2*)g_wv2, (long long)PP*CC*CC/4);

    // fused pool + packed transpose + xd row sums
    pool2_kernel<<<dim3(CC/32, BB, PP), 256>>>(x, g_xdT2, g_xsum);

    // u = Wv @ xd  (bf16 mma, M=2048, N=3072, K=2048, packed bf16x2 output)
    bmma_gemm<1><<<dim3(BN3/128, CC/128, PP), 128, BG_SMEM>>>(
        g_wv2, g_xdT2, g_u2, nullptr, BN3, CCW,
        (long long)CC*CCW, (long long)BN3*CCW, (long long)CC*BN3W, 0);

    // qk = Wqk' @ xd + b'   (bf16 mma, M=256, N=3072, K=2048)
    bmma_gemm<0><<<dim3(BN3/128, 256/128, PP), 128, BG_SMEM>>>(
        g_wqk2, g_xdT2, g_qk, g_qkb, BN3, CCW,
        (long long)256*CCW, (long long)BN3*CCW, (long long)256*BN3, 256);

    // attention -> packed attn2
    attn_kernel<<<BB*PP, 256, 2*ICC*NN*4>>>(g_qk, g_attn2);

    // ao = u @ attnT + vb (bf16x2 out), fused GAP
    aoatt_kernel<<<dim3(CC/128, BB, PP), 128>>>(
        g_u2, g_attn2, pa_v_b, pa_gamma, g_xsum, g_ao2, g_gap);

    // SE block
    sgemm_k<64,32,16,4,2,1><<<dim3(1, C4/64, PP), 256>>>(
        ca_fc1_w, g_gap, g_h1, ca_fc1_b, C4, BB, CC,
        (long long)C4*CC, (long long)CC*BB, (long long)C4*BB, C4);
    sgemm_k<64,32,16,4,2,2><<<dim3(1, CC/64, PP), 256>>>(
        ca_fc2_w, g_h1, g_cw, ca_fc2_b, CC, BB, C4,
        (long long)CC*C4, (long long)C4*BB, (long long)CC*BB, CC);

    // fused upsample + residual + SE + gate
    final_kernel<<<dim3(CC/4, BB*PP), 384>>>(x, g_ao2, g_cw, g_mw, pa_gamma, ca_gamma, out);
}